// round 3
// baseline (speedup 1.0000x reference)
#include <cuda_runtime.h>
#include <math.h>

#define NROI 4096
#define DIM  1024
#define HID  512
#define NCLS 21
#define NBBX 84          // 4*21
#define NW   128         // adjacency words per row (4096/32)
#define KSPLIT 8

typedef unsigned long long ULL;

// ---------------- scratch (static device globals; no allocation) -------------
__device__ float    g_xn[NROI * DIM];
__device__ float    g_d[NROI];
__device__ float    g_t1[NROI * HID];
__device__ float    g_u1[DIM * HID];
__device__ float    g_u2[DIM * HID];
__device__ float    g_upart[KSPLIT * DIM * HID];
__device__ float    g_h1[NROI * HID];
__device__ float    g_t2[NROI * HID];
__device__ float    g_h2[NROI * HID];
__device__ unsigned g_adj[NROI * NW];
__device__ int      g_lab[2][NROI];
__device__ float    g_logits[NROI * NCLS];
__device__ int      g_conv;
__device__ int      g_diffs[33];

// ---------------- adjacency bitmask: bit set iff IoU > 0 (i != j) ------------
// One lane per candidate j; word built with ballot. Boxes staged in smem.
__global__ void __launch_bounds__(256) adj_kernel(const float* __restrict__ rois) {
    __shared__ float4 sbox[2048];
    __shared__ float4 rbox[16];
    int tid = threadIdx.x;
    int r0 = blockIdx.x * 16;
    if (tid < 16) rbox[tid] = *reinterpret_cast<const float4*>(&rois[(r0 + tid) * 4]);
    const float4* g4 = reinterpret_cast<const float4*>(rois);
    int warp = tid >> 5, lane = tid & 31;
#pragma unroll
    for (int half = 0; half < 2; half++) {
        __syncthreads();
        for (int k = tid; k < 2048; k += 256) sbox[k] = g4[half * 2048 + k];
        __syncthreads();
        for (int t = warp; t < 1024; t += 8) {
            int r = t >> 6, wl = t & 63;
            float4 bi = rbox[r];
            float4 bj = sbox[wl * 32 + lane];
            int i = r0 + r;
            int j = half * 2048 + wl * 32 + lane;
            float iw = fminf(bi.z, bj.z) - fmaxf(bi.x, bj.x) + 1.0f;
            float ih = fminf(bi.w, bj.w) - fmaxf(bi.y, bj.y) + 1.0f;
            unsigned bits = __ballot_sync(0xffffffffu,
                                          iw > 0.0f && ih > 0.0f && j != i);
            if (lane == 0) g_adj[(size_t)i * NW + half * 64 + wl] = bits;
        }
    }
}

__global__ void init_labels_kernel() {
    int i = blockIdx.x * blockDim.x + threadIdx.x;
    if (i < NROI) g_lab[0][i] = i;
    if (i < 33) g_diffs[i] = 0;
    if (i == 33) g_conv = 0;
}

// One reference iteration = P(J(l)); final standalone J applied at output.
// Convergence: launch it reads slot it-1 (written entirely by previous launch).
__global__ void __launch_bounds__(256) prop_kernel(int it, int src) {
    if (*(volatile int*)&g_conv) return;
    if (it > 0 && *(volatile int*)&g_diffs[it - 1] == 0) { g_conv = 1; return; }
    __shared__ int slj[NROI];
    __shared__ int wmin[NW];
    const int* __restrict__ lp = g_lab[src];
    int* __restrict__ lo = g_lab[src ^ 1];
    int tid = threadIdx.x;
    for (int k = tid; k < NROI; k += 256) slj[k] = lp[lp[k]];
    __syncthreads();
    if (tid < NW) {
        int m = slj[tid * 32];
#pragma unroll
        for (int b = 1; b < 32; b++) m = min(m, slj[tid * 32 + b]);
        wmin[tid] = m;
    }
    __syncthreads();
    int warp = tid >> 5, lane = tid & 31;
    int rbase = blockIdx.x * 32 + warp * 4;
#pragma unroll
    for (int r = 0; r < 4; r++) {
        int i = rbase + r;
        const unsigned* __restrict__ arow = &g_adj[(size_t)i * NW];
        int nb = slj[i];
#pragma unroll
        for (int q = 0; q < 4; q++) {
            int w = lane + q * 32;
            unsigned wb = arow[w];
            if (wb == 0xFFFFFFFFu) {
                nb = min(nb, wmin[w]);
            } else {
                while (wb) {
                    int b = __ffs(wb) - 1;
                    wb &= wb - 1;
                    nb = min(nb, slj[w * 32 + b]);
                }
            }
        }
#pragma unroll
        for (int o = 16; o; o >>= 1) nb = min(nb, __shfl_xor_sync(0xffffffffu, nb, o));
        if (lane == 0) {
            lo[i] = nb;
            if (nb != lp[i]) g_diffs[it] = 1;
        }
    }
}

__global__ void labels_out_kernel(float* __restrict__ out) {
    int i = blockIdx.x * blockDim.x + threadIdx.x;
    if (i < NROI) {
        int v = g_lab[0][i];
        out[i] = (float)g_lab[0][v];        // final pointer jump + cast
    }
}

// ---------------- row-normalize pooled_feat; d_i = xn_i . xn_i ---------------
__global__ void normalize_kernel(const float* __restrict__ pf) {
    __shared__ float red[256];
    int row = blockIdx.x;
    const float4* x = reinterpret_cast<const float4*>(pf + (size_t)row * DIM);
    float4 v = x[threadIdx.x];
    float ss = v.x * v.x + v.y * v.y + v.z * v.z + v.w * v.w;
    red[threadIdx.x] = ss;
    __syncthreads();
    for (int s = 128; s > 0; s >>= 1) {
        if (threadIdx.x < s) red[threadIdx.x] += red[threadIdx.x + s];
        __syncthreads();
    }
    float tot = red[0];
    float sc = 1.0f / fmaxf(sqrtf(tot), 1e-6f);
    float4 o = make_float4(v.x * sc, v.y * sc, v.z * sc, v.w * sc);
    reinterpret_cast<float4*>(g_xn + (size_t)row * DIM)[threadIdx.x] = o;
    if (threadIdx.x == 0) g_d[row] = (tot * sc) * sc;
}

// ---------------- f32x2 packed-FMA GEMM, 128x64 tile, 8x8/thread -------------
__device__ __forceinline__ void fma2(ULL& d, ULL a, ULL b) {
    asm("fma.rn.f32x2 %0, %1, %2, %0;" : "+l"(d) : "l"(a), "l"(b));
}
__device__ __forceinline__ ULL dup2(float b) {
    ULL r;
    asm("mov.b64 %0, {%1, %1};" : "=l"(r) : "f"(b));
    return r;
}
__device__ __forceinline__ float2 unpk(ULL v) {
    unsigned lo = (unsigned)v, hi = (unsigned)(v >> 32);
    return make_float2(__uint_as_float(lo), __uint_as_float(hi));
}

#define GBM 128
#define GBN 64
#define GBK 16
#define APAD 132    // floats per As row (528B)
#define BPAD 66     // ULLs per Bs row (528B)

// C[M,N] = A @ B  (A[m*lda+k], or A[k*lda+m] if TA). M%128==0, N%64==0, K%16==0.
// EPI 0: store   EPI 1: relu(acc - d[m]*T[m*ldc+n] + bias[n])
template<bool TA, int EPI>
__global__ void __launch_bounds__(128) gemm3_kernel(
    const float* __restrict__ A, const float* __restrict__ B, float* __restrict__ C,
    int M, int N, int K, int lda, int ldb, int ldc, int kChunk,
    const float* __restrict__ bias, const float* __restrict__ dvec,
    const float* __restrict__ Tm)
{
    __shared__ __align__(16) float As[2][GBK][APAD];
    __shared__ __align__(16) ULL   Bs[2][GBK][BPAD];
    int m0 = blockIdx.y * GBM;
    int n0 = blockIdx.x * GBN;
    int k0 = blockIdx.z * kChunk;
    int kEnd = min(K, k0 + kChunk);
    if (gridDim.z > 1) C += (size_t)blockIdx.z * M * ldc;
    int tid = threadIdx.x;
    int tx = tid & 7;        // 8 n each -> 64
    int ty = tid >> 3;       // 8 m each -> 128

    // loader indices
    int arow = tid >> 2, akq = (tid & 3) << 2;   // !TA: 4 rows (arow+32i), k quad
    int akk = tid >> 3, amq = tid & 7;           // TA: k row, 16-m segment
    int bkk = tid >> 3, bnq = tid & 7;           // B: k row, 8-n segment

    ULL acc[4][8];
#pragma unroll
    for (int i = 0; i < 4; i++)
#pragma unroll
        for (int j = 0; j < 8; j++) acc[i][j] = 0ULL;

    float4 a0, a1, a2, a3, b0, b1;

    auto LOADG = [&](int kt) {
        if (!TA) {
            const float* ap = A + (size_t)(m0 + arow) * lda + kt + akq;
            a0 = *reinterpret_cast<const float4*>(ap);
            a1 = *reinterpret_cast<const float4*>(ap + (size_t)32 * lda);
            a2 = *reinterpret_cast<const float4*>(ap + (size_t)64 * lda);
            a3 = *reinterpret_cast<const float4*>(ap + (size_t)96 * lda);
        } else {
            const float* ap = A + (size_t)(kt + akk) * lda + m0 + amq * 16;
            a0 = *reinterpret_cast<const float4*>(ap);
            a1 = *reinterpret_cast<const float4*>(ap + 4);
            a2 = *reinterpret_cast<const float4*>(ap + 8);
            a3 = *reinterpret_cast<const float4*>(ap + 12);
        }
        const float* bp = B + (size_t)(kt + bkk) * ldb + n0 + bnq * 8;
        b0 = *reinterpret_cast<const float4*>(bp);
        b1 = *reinterpret_cast<const float4*>(bp + 4);
    };
    auto STORES = [&](int bf) {
        if (!TA) {
            As[bf][akq + 0][arow]      = a0.x; As[bf][akq + 1][arow]      = a0.y;
            As[bf][akq + 2][arow]      = a0.z; As[bf][akq + 3][arow]      = a0.w;
            As[bf][akq + 0][arow + 32] = a1.x; As[bf][akq + 1][arow + 32] = a1.y;
            As[bf][akq + 2][arow + 32] = a1.z; As[bf][akq + 3][arow + 32] = a1.w;
            As[bf][akq + 0][arow + 64] = a2.x; As[bf][akq + 1][arow + 64] = a2.y;
            As[bf][akq + 2][arow + 64] = a2.z; As[bf][akq + 3][arow + 64] = a2.w;
            As[bf][akq + 0][arow + 96] = a3.x; As[bf][akq + 1][arow + 96] = a3.y;
            As[bf][akq + 2][arow + 96] = a3.z; As[bf][akq + 3][arow + 96] = a3.w;
        } else {
            *reinterpret_cast<float4*>(&As[bf][akk][amq * 16 + 0])  = a0;
            *reinterpret_cast<float4*>(&As[bf][akk][amq * 16 + 4])  = a1;
            *reinterpret_cast<float4*>(&As[bf][akk][amq * 16 + 8])  = a2;
            *reinterpret_cast<float4*>(&As[bf][akk][amq * 16 + 12]) = a3;
        }
        ULL* bd = &Bs[bf][bkk][bnq * 8];
        bd[0] = dup2(b0.x); bd[1] = dup2(b0.y); bd[2] = dup2(b0.z); bd[3] = dup2(b0.w);
        bd[4] = dup2(b1.x); bd[5] = dup2(b1.y); bd[6] = dup2(b1.z); bd[7] = dup2(b1.w);
    };

    LOADG(k0);
    STORES(0);
    __syncthreads();
    int buf = 0;
    for (int kt = k0; kt < kEnd; kt += GBK) {
        bool more = (kt + GBK) < kEnd;
        if (more) LOADG(kt + GBK);
#pragma unroll
        for (int kk = 0; kk < GBK; kk++) {
            const ULL* ap = reinterpret_cast<const ULL*>(&As[buf][kk][ty * 8]);
            ULL A0 = ap[0], A1 = ap[1], A2 = ap[2], A3 = ap[3];
            const ULL* bp = &Bs[buf][kk][tx * 8];
            ULL B0 = bp[0], B1 = bp[1], B2 = bp[2], B3 = bp[3];
            ULL B4 = bp[4], B5 = bp[5], B6 = bp[6], B7 = bp[7];
            fma2(acc[0][0], A0, B0); fma2(acc[0][1], A0, B1);
            fma2(acc[0][2], A0, B2); fma2(acc[0][3], A0, B3);
            fma2(acc[0][4], A0, B4); fma2(acc[0][5], A0, B5);
            fma2(acc[0][6], A0, B6); fma2(acc[0][7], A0, B7);
            fma2(acc[1][0], A1, B0); fma2(acc[1][1], A1, B1);
            fma2(acc[1][2], A1, B2); fma2(acc[1][3], A1, B3);
            fma2(acc[1][4], A1, B4); fma2(acc[1][5], A1, B5);
            fma2(acc[1][6], A1, B6); fma2(acc[1][7], A1, B7);
            fma2(acc[2][0], A2, B0); fma2(acc[2][1], A2, B1);
            fma2(acc[2][2], A2, B2); fma2(acc[2][3], A2, B3);
            fma2(acc[2][4], A2, B4); fma2(acc[2][5], A2, B5);
            fma2(acc[2][6], A2, B6); fma2(acc[2][7], A2, B7);
            fma2(acc[3][0], A3, B0); fma2(acc[3][1], A3, B1);
            fma2(acc[3][2], A3, B2); fma2(acc[3][3], A3, B3);
            fma2(acc[3][4], A3, B4); fma2(acc[3][5], A3, B5);
            fma2(acc[3][6], A3, B6); fma2(acc[3][7], A3, B7);
        }
        if (more) STORES(buf ^ 1);
        __syncthreads();
        buf ^= 1;
    }

    float4 bias_lo, bias_hi;
    if (EPI == 1) {
        bias_lo = *reinterpret_cast<const float4*>(&bias[n0 + tx * 8]);
        bias_hi = *reinterpret_cast<const float4*>(&bias[n0 + tx * 8 + 4]);
    }
#pragma unroll
    for (int ip = 0; ip < 4; ip++) {
#pragma unroll
        for (int half = 0; half < 2; half++) {
            int gm = m0 + ty * 8 + ip * 2 + half;
            float r[8];
#pragma unroll
            for (int j = 0; j < 8; j++) {
                float2 p = unpk(acc[ip][j]);
                r[j] = half ? p.y : p.x;
            }
            float* crow = &C[(size_t)gm * ldc + n0 + tx * 8];
            if (EPI == 1) {
                float dv = dvec[gm];
                const float* trow = &Tm[(size_t)gm * ldc + n0 + tx * 8];
                float4 t_lo = *reinterpret_cast<const float4*>(trow);
                float4 t_hi = *reinterpret_cast<const float4*>(trow + 4);
                float4 o_lo, o_hi;
                o_lo.x = fmaxf(r[0] - dv * t_lo.x + bias_lo.x, 0.f);
                o_lo.y = fmaxf(r[1] - dv * t_lo.y + bias_lo.y, 0.f);
                o_lo.z = fmaxf(r[2] - dv * t_lo.z + bias_lo.z, 0.f);
                o_lo.w = fmaxf(r[3] - dv * t_lo.w + bias_lo.w, 0.f);
                o_hi.x = fmaxf(r[4] - dv * t_hi.x + bias_hi.x, 0.f);
                o_hi.y = fmaxf(r[5] - dv * t_hi.y + bias_hi.y, 0.f);
                o_hi.z = fmaxf(r[6] - dv * t_hi.z + bias_hi.z, 0.f);
                o_hi.w = fmaxf(r[7] - dv * t_hi.w + bias_hi.w, 0.f);
                *reinterpret_cast<float4*>(crow)     = o_lo;
                *reinterpret_cast<float4*>(crow + 4) = o_hi;
            } else {
                *reinterpret_cast<float4*>(crow)     = make_float4(r[0], r[1], r[2], r[3]);
                *reinterpret_cast<float4*>(crow + 4) = make_float4(r[4], r[5], r[6], r[7]);
            }
        }
    }
}

// ---------------- small fallback GEMM (guarded, for N=84 / N=21 heads) -------
#define BM 64
#define BN 64
#define BK 16
#define SPAD 68
__global__ void __launch_bounds__(256) gemm_small_kernel(
    const float* __restrict__ A, const float* __restrict__ B, float* __restrict__ C,
    int M, int N, int K, int lda, int ldb, int ldc,
    const float* __restrict__ bias)
{
    __shared__ __align__(16) float As[BK][SPAD];
    __shared__ __align__(16) float Bs[BK][SPAD];
    int m0 = blockIdx.y * BM;
    int n0 = blockIdx.x * BN;
    int tid = threadIdx.x;
    int tx = tid & 15, ty = tid >> 4;
    float acc[4][4] = {};
    for (int kt = 0; kt < K; kt += BK) {
        {
            int kk = tid & 15, mm = tid >> 4;
#pragma unroll
            for (int p = 0; p < 4; p++) {
                int m = mm + p * 16;
                As[kk][m] = A[(size_t)(m0 + m) * lda + (kt + kk)];
            }
        }
        {
            int nn = tid & 63, kk = tid >> 6;
#pragma unroll
            for (int p = 0; p < 4; p++) {
                int k = kk + p * 4;
                int gn = n0 + nn;
                Bs[k][nn] = (gn < N) ? B[(size_t)(kt + k) * ldb + gn] : 0.f;
            }
        }
        __syncthreads();
#pragma unroll
        for (int kk = 0; kk < BK; kk++) {
            float4 a4 = *reinterpret_cast<const float4*>(&As[kk][ty * 4]);
            float4 b4 = *reinterpret_cast<const float4*>(&Bs[kk][tx * 4]);
            float a[4] = {a4.x, a4.y, a4.z, a4.w};
            float b[4] = {b4.x, b4.y, b4.z, b4.w};
#pragma unroll
            for (int i = 0; i < 4; i++)
#pragma unroll
                for (int j = 0; j < 4; j++)
                    acc[i][j] = fmaf(a[i], b[j], acc[i][j]);
        }
        __syncthreads();
    }
#pragma unroll
    for (int i = 0; i < 4; i++) {
        int gm = m0 + ty * 4 + i;
#pragma unroll
        for (int j = 0; j < 4; j++) {
            int gn = n0 + tx * 4 + j;
            if (gn < N) C[(size_t)gm * ldc + gn] = acc[i][j] + bias[gn];
        }
    }
}

__global__ void reduceK_kernel(const float* __restrict__ part, float* __restrict__ outb,
                               int total, int parts) {
    int i = blockIdx.x * blockDim.x + threadIdx.x;
    if (i >= total) return;
    float s = 0.f;
    for (int p = 0; p < parts; p++) s += part[(size_t)p * total + i];
    outb[i] = s;
}

// ---------------- softmax over 21 classes, one warp per row ------------------
__global__ void softmax_kernel(float* __restrict__ out) {
    int row = blockIdx.x * 8 + (threadIdx.x >> 5);
    int lane = threadIdx.x & 31;
    if (row >= NROI) return;
    float v = (lane < NCLS) ? g_logits[row * NCLS + lane] : -INFINITY;
    float m = v;
#pragma unroll
    for (int o = 16; o; o >>= 1) m = fmaxf(m, __shfl_xor_sync(0xffffffffu, m, o));
    float e = (lane < NCLS) ? expf(v - m) : 0.f;
    float s = e;
#pragma unroll
    for (int o = 16; o; o >>= 1) s += __shfl_xor_sync(0xffffffffu, s, o);
    if (lane < NCLS) out[NROI + row * NCLS + lane] = e / s;
}

// -----------------------------------------------------------------------------
extern "C" void kernel_launch(void* const* d_in, const int* in_sizes, int n_in,
                              void* d_out, int out_size) {
    const float* rois   = (const float*)d_in[0];
    const float* pf     = (const float*)d_in[1];
    const float* Wg1    = (const float*)d_in[2];
    const float* bg1    = (const float*)d_in[3];
    const float* Wg2    = (const float*)d_in[4];
    const float* bg2    = (const float*)d_in[5];
    const float* W_bbox = (const float*)d_in[6];
    const float* b_bbox = (const float*)d_in[7];
    const float* W_cls  = (const float*)d_in[8];
    const float* b_cls  = (const float*)d_in[9];
    float* out = (float*)d_out;

    float *xn, *dv, *t1, *u1, *u2, *upart, *h1, *t2, *h2, *logits;
    cudaGetSymbolAddress((void**)&xn,     g_xn);
    cudaGetSymbolAddress((void**)&dv,     g_d);
    cudaGetSymbolAddress((void**)&t1,     g_t1);
    cudaGetSymbolAddress((void**)&u1,     g_u1);
    cudaGetSymbolAddress((void**)&u2,     g_u2);
    cudaGetSymbolAddress((void**)&upart,  g_upart);
    cudaGetSymbolAddress((void**)&h1,     g_h1);
    cudaGetSymbolAddress((void**)&t2,     g_t2);
    cudaGetSymbolAddress((void**)&h2,     g_h2);
    cudaGetSymbolAddress((void**)&logits, g_logits);

    const int utotal = DIM * HID;

    // Launch order chosen so ncu (-s 5 -c 1) profiles h1 (launch #6).
    normalize_kernel<<<NROI, 256>>>(pf);                               // 1
    adj_kernel<<<NROI / 16, 256>>>(rois);                              // 2

    // t1 = pooled @ Wg1     [4096,512] K=1024
    gemm3_kernel<false, 0><<<dim3(HID / GBN, NROI / GBM, 1), 128>>>(   // 3
        pf, Wg1, t1, NROI, HID, DIM, DIM, HID, HID, DIM, nullptr, nullptr, nullptr);

    // u1 = xn^T @ t1        [1024,512] K=4096, split-K
    gemm3_kernel<true, 0><<<dim3(HID / GBN, DIM / GBM, KSPLIT), 128>>>( // 4
        xn, t1, upart, DIM, HID, NROI, DIM, HID, HID, NROI / KSPLIT,
        nullptr, nullptr, nullptr);
    reduceK_kernel<<<(utotal + 255) / 256, 256>>>(upart, u1, utotal, KSPLIT); // 5

    // h1 = relu(xn @ u1 - d*t1 + bg1)
    gemm3_kernel<false, 1><<<dim3(HID / GBN, NROI / GBM, 1), 128>>>(   // 6 <- profiled
        xn, u1, h1, NROI, HID, DIM, DIM, HID, HID, DIM, bg1, dv, t1);

    // t2 = h1 @ Wg2         [4096,512] K=512
    gemm3_kernel<false, 0><<<dim3(HID / GBN, NROI / GBM, 1), 128>>>(
        h1, Wg2, t2, NROI, HID, HID, HID, HID, HID, HID, nullptr, nullptr, nullptr);

    // u2 = xn^T @ t2
    gemm3_kernel<true, 0><<<dim3(HID / GBN, DIM / GBM, KSPLIT), 128>>>(
        xn, t2, upart, DIM, HID, NROI, DIM, HID, HID, NROI / KSPLIT,
        nullptr, nullptr, nullptr);
    reduceK_kernel<<<(utotal + 255) / 256, 256>>>(upart, u2, utotal, KSPLIT);

    // h2 = relu(xn @ u2 - d*t2 + bg2)
    gemm3_kernel<false, 1><<<dim3(HID / GBN, NROI / GBM, 1), 128>>>(
        xn, u2, h2, NROI, HID, DIM, DIM, HID, HID, DIM, bg2, dv, t2);

    // bbox_pred = h2 @ W_bbox + b_bbox
    gemm_small_kernel<<<dim3((NBBX + BN - 1) / BN, NROI / BM, 1), 256>>>(
        h2, W_bbox, out + NROI + (size_t)NROI * NCLS,
        NROI, NBBX, HID, HID, NBBX, NBBX, b_bbox);

    // cls logits + softmax
    gemm_small_kernel<<<dim3(1, NROI / BM, 1), 256>>>(
        h2, W_cls, logits, NROI, NCLS, HID, HID, NCLS, NCLS, b_cls);
    softmax_kernel<<<NROI / 8, 256>>>(out);

    // ---- connected components (32 fused prop iterations, early exit) ----
    init_labels_kernel<<<17, 256>>>();
    for (int it = 0; it < 32; it++)
        prop_kernel<<<NROI / 32, 256>>>(it, it & 1);
    labels_out_kernel<<<16, 256>>>(out);
}

// round 4
// speedup vs baseline: 2.4742x; 2.4742x over previous
#include <cuda_runtime.h>
#include <math.h>

#define NROI 4096
#define DIM  1024
#define HID  512
#define NCLS 21
#define NBBX 84          // 4*21
#define NW   128         // adjacency words per row (4096/32)
#define KSPLIT 8

typedef unsigned long long ULL;

// ---------------- scratch (static device globals; no allocation) -------------
__device__ float    g_xn[NROI * DIM];
__device__ float    g_d[NROI];
__device__ float    g_t1[NROI * HID];
__device__ float    g_u1[DIM * HID];
__device__ float    g_u2[DIM * HID];
__device__ float    g_upart[KSPLIT * DIM * HID];
__device__ float    g_h1[NROI * HID];
__device__ float    g_t2[NROI * HID];
__device__ float    g_h2[NROI * HID];
__device__ unsigned g_adj[NROI * NW];
__device__ int      g_lab[2][NROI];
__device__ float    g_logits[NROI * NCLS];
__device__ int      g_conv;
__device__ int      g_diffs[33];

// ---------------- adjacency bitmask: bit set iff IoU > 0 (i != j) ------------
__global__ void __launch_bounds__(256) adj_kernel(const float* __restrict__ rois) {
    __shared__ float4 sbox[2048];
    __shared__ float4 rbox[16];
    int tid = threadIdx.x;
    int r0 = blockIdx.x * 16;
    if (tid < 16) rbox[tid] = *reinterpret_cast<const float4*>(&rois[(r0 + tid) * 4]);
    const float4* g4 = reinterpret_cast<const float4*>(rois);
    int warp = tid >> 5, lane = tid & 31;
#pragma unroll
    for (int half = 0; half < 2; half++) {
        __syncthreads();
        for (int k = tid; k < 2048; k += 256) sbox[k] = g4[half * 2048 + k];
        __syncthreads();
        for (int t = warp; t < 1024; t += 8) {
            int r = t >> 6, wl = t & 63;
            float4 bi = rbox[r];
            float4 bj = sbox[wl * 32 + lane];
            int i = r0 + r;
            int j = half * 2048 + wl * 32 + lane;
            float iw = fminf(bi.z, bj.z) - fmaxf(bi.x, bj.x) + 1.0f;
            float ih = fminf(bi.w, bj.w) - fmaxf(bi.y, bj.y) + 1.0f;
            unsigned bits = __ballot_sync(0xffffffffu,
                                          iw > 0.0f && ih > 0.0f && j != i);
            if (lane == 0) g_adj[(size_t)i * NW + half * 64 + wl] = bits;
        }
    }
}

__global__ void init_labels_kernel() {
    int i = blockIdx.x * blockDim.x + threadIdx.x;
    if (i < NROI) g_lab[0][i] = i;
    if (i < 33) g_diffs[i] = 0;
    if (i == 33) g_conv = 0;
}

// One reference iteration = P(J(l)); final standalone J applied at output.
// Convergence: launch it reads slot it-1 (written entirely by previous launch).
__global__ void __launch_bounds__(256) prop_kernel(int it, int src) {
    if (*(volatile int*)&g_conv) return;
    if (it > 0 && *(volatile int*)&g_diffs[it - 1] == 0) { g_conv = 1; return; }
    __shared__ int slj[NROI];
    __shared__ int wmin[NW];
    const int* __restrict__ lp = g_lab[src];
    int* __restrict__ lo = g_lab[src ^ 1];
    int tid = threadIdx.x;
    for (int k = tid; k < NROI; k += 256) slj[k] = lp[lp[k]];
    __syncthreads();
    if (tid < NW) {
        int m = slj[tid * 32];
#pragma unroll
        for (int b = 1; b < 32; b++) m = min(m, slj[tid * 32 + b]);
        wmin[tid] = m;
    }
    __syncthreads();
    int warp = tid >> 5, lane = tid & 31;
    int rbase = blockIdx.x * 32 + warp * 4;
#pragma unroll
    for (int r = 0; r < 4; r++) {
        int i = rbase + r;
        const unsigned* __restrict__ arow = &g_adj[(size_t)i * NW];
        int nb = slj[i];
#pragma unroll
        for (int q = 0; q < 4; q++) {
            int w = lane + q * 32;
            unsigned wb = arow[w];
            if (wb == 0xFFFFFFFFu) {
                nb = min(nb, wmin[w]);
            } else {
                while (wb) {
                    int b = __ffs(wb) - 1;
                    wb &= wb - 1;
                    nb = min(nb, slj[w * 32 + b]);
                }
            }
        }
#pragma unroll
        for (int o = 16; o; o >>= 1) nb = min(nb, __shfl_xor_sync(0xffffffffu, nb, o));
        if (lane == 0) {
            lo[i] = nb;
            if (nb != lp[i]) g_diffs[it] = 1;
        }
    }
}

__global__ void labels_out_kernel(float* __restrict__ out) {
    int i = blockIdx.x * blockDim.x + threadIdx.x;
    if (i < NROI) {
        int v = g_lab[0][i];
        out[i] = (float)g_lab[0][v];        // final pointer jump + cast
    }
}

// ---------------- row-normalize pooled_feat; d_i = xn_i . xn_i ---------------
__global__ void normalize_kernel(const float* __restrict__ pf) {
    __shared__ float red[256];
    int row = blockIdx.x;
    const float4* x = reinterpret_cast<const float4*>(pf + (size_t)row * DIM);
    float4 v = x[threadIdx.x];
    float ss = v.x * v.x + v.y * v.y + v.z * v.z + v.w * v.w;
    red[threadIdx.x] = ss;
    __syncthreads();
    for (int s = 128; s > 0; s >>= 1) {
        if (threadIdx.x < s) red[threadIdx.x] += red[threadIdx.x + s];
        __syncthreads();
    }
    float tot = red[0];
    float sc = 1.0f / fmaxf(sqrtf(tot), 1e-6f);
    float4 o = make_float4(v.x * sc, v.y * sc, v.z * sc, v.w * sc);
    reinterpret_cast<float4*>(g_xn + (size_t)row * DIM)[threadIdx.x] = o;
    if (threadIdx.x == 0) g_d[row] = (tot * sc) * sc;
}

// ---------------- f32x2 packed-FMA GEMM, 128x64 tile, 256 thr, 8mx4n ---------
__device__ __forceinline__ void fma2(ULL& d, ULL a, ULL b) {
    asm("fma.rn.f32x2 %0, %1, %2, %0;" : "+l"(d) : "l"(a), "l"(b));
}
__device__ __forceinline__ ULL dup2(float b) {
    ULL r;
    asm("mov.b64 %0, {%1, %1};" : "=l"(r) : "f"(b));
    return r;
}
__device__ __forceinline__ float2 unpk(ULL v) {
    unsigned lo = (unsigned)v, hi = (unsigned)(v >> 32);
    return make_float2(__uint_as_float(lo), __uint_as_float(hi));
}

#define GBM 128
#define GBN 64
#define GBK 16
#define APAD 132
#define BPAD 68

// C[M,N] = A @ B  (A[m*lda+k], or A[k*lda+m] if TA). M%128==0, N%64==0, K%16==0.
// EPI 0: store   EPI 1: relu(acc - d[m]*T[m*ldc+n] + bias[n])
template<bool TA, int EPI>
__global__ void __launch_bounds__(256) gemm2_kernel(
    const float* __restrict__ A, const float* __restrict__ B, float* __restrict__ C,
    int M, int N, int K, int lda, int ldb, int ldc, int kChunk,
    const float* __restrict__ bias, const float* __restrict__ dvec,
    const float* __restrict__ Tm)
{
    __shared__ __align__(16) float As[2][GBK][APAD];
    __shared__ __align__(16) float Bs[2][GBK][BPAD];
    int m0 = blockIdx.y * GBM;
    int n0 = blockIdx.x * GBN;
    int k0 = blockIdx.z * kChunk;
    int kEnd = min(K, k0 + kChunk);
    if (gridDim.z > 1) C += (size_t)blockIdx.z * M * ldc;
    int tid = threadIdx.x;
    int tx = tid & 15, ty = tid >> 4;        // tx: 4n each, ty: 8m each

    // loader indices
    int arow = tid >> 1, akq = (tid & 1) * 4;   // !TA
    int akk = tid >> 4, amq = tid & 15;         // TA
    int bkb = tid >> 4, bnq = tid & 15;         // B

    ULL acc[4][4];                              // [m-pair][n]
#pragma unroll
    for (int i = 0; i < 4; i++)
#pragma unroll
        for (int j = 0; j < 4; j++) acc[i][j] = 0ULL;

    float4 ra0, ra1, rb0;

    auto LOADG = [&](int kt) {
        if (!TA) {
            const float* ap = A + (size_t)(m0 + arow) * lda + kt + akq;
            ra0 = *reinterpret_cast<const float4*>(ap);
            ra1 = *reinterpret_cast<const float4*>(ap + 8);
        } else {
            const float* ap = A + (size_t)(kt + akk) * lda + m0 + amq * 8;
            ra0 = *reinterpret_cast<const float4*>(ap);
            ra1 = *reinterpret_cast<const float4*>(ap + 4);
        }
        rb0 = *reinterpret_cast<const float4*>(
            B + (size_t)(kt + bkb) * ldb + n0 + bnq * 4);
    };
    auto STORES = [&](int bf) {
        if (!TA) {
            As[bf][akq + 0][arow] = ra0.x; As[bf][akq + 1][arow] = ra0.y;
            As[bf][akq + 2][arow] = ra0.z; As[bf][akq + 3][arow] = ra0.w;
            As[bf][akq + 8][arow] = ra1.x; As[bf][akq + 9][arow] = ra1.y;
            As[bf][akq + 10][arow] = ra1.z; As[bf][akq + 11][arow] = ra1.w;
        } else {
            *reinterpret_cast<float4*>(&As[bf][akk][amq * 8 + 0]) = ra0;
            *reinterpret_cast<float4*>(&As[bf][akk][amq * 8 + 4]) = ra1;
        }
        *reinterpret_cast<float4*>(&Bs[bf][bkb][bnq * 4]) = rb0;
    };

    LOADG(k0);
    STORES(0);
    __syncthreads();
    int buf = 0;
    for (int kt = k0; kt < kEnd; kt += GBK) {
        bool more = (kt + GBK) < kEnd;
        if (more) LOADG(kt + GBK);
#pragma unroll
        for (int kk = 0; kk < GBK; kk++) {
            const ULL* ap = reinterpret_cast<const ULL*>(&As[buf][kk][ty * 8]);
            ULL a0 = ap[0], a1 = ap[1], a2 = ap[2], a3 = ap[3];
            float4 b4 = *reinterpret_cast<const float4*>(&Bs[buf][kk][tx * 4]);
            ULL bd0 = dup2(b4.x), bd1 = dup2(b4.y);
            ULL bd2 = dup2(b4.z), bd3 = dup2(b4.w);
            fma2(acc[0][0], a0, bd0); fma2(acc[0][1], a0, bd1);
            fma2(acc[0][2], a0, bd2); fma2(acc[0][3], a0, bd3);
            fma2(acc[1][0], a1, bd0); fma2(acc[1][1], a1, bd1);
            fma2(acc[1][2], a1, bd2); fma2(acc[1][3], a1, bd3);
            fma2(acc[2][0], a2, bd0); fma2(acc[2][1], a2, bd1);
            fma2(acc[2][2], a2, bd2); fma2(acc[2][3], a2, bd3);
            fma2(acc[3][0], a3, bd0); fma2(acc[3][1], a3, bd1);
            fma2(acc[3][2], a3, bd2); fma2(acc[3][3], a3, bd3);
        }
        if (more) STORES(buf ^ 1);
        __syncthreads();
        buf ^= 1;
    }

    float4 bias4;
    if (EPI == 1) bias4 = *reinterpret_cast<const float4*>(&bias[n0 + tx * 4]);
#pragma unroll
    for (int ip = 0; ip < 4; ip++) {
#pragma unroll
        for (int half = 0; half < 2; half++) {
            int gm = m0 + ty * 8 + ip * 2 + half;
            float r0 = half ? unpk(acc[ip][0]).y : unpk(acc[ip][0]).x;
            float r1 = half ? unpk(acc[ip][1]).y : unpk(acc[ip][1]).x;
            float r2 = half ? unpk(acc[ip][2]).y : unpk(acc[ip][2]).x;
            float r3 = half ? unpk(acc[ip][3]).y : unpk(acc[ip][3]).x;
            float4 res;
            if (EPI == 1) {
                float dv = dvec[gm];
                float4 tm = *reinterpret_cast<const float4*>(
                    &Tm[(size_t)gm * ldc + n0 + tx * 4]);
                res.x = fmaxf(r0 - dv * tm.x + bias4.x, 0.f);
                res.y = fmaxf(r1 - dv * tm.y + bias4.y, 0.f);
                res.z = fmaxf(r2 - dv * tm.z + bias4.z, 0.f);
                res.w = fmaxf(r3 - dv * tm.w + bias4.w, 0.f);
            } else {
                res = make_float4(r0, r1, r2, r3);
            }
            *reinterpret_cast<float4*>(&C[(size_t)gm * ldc + n0 + tx * 4]) = res;
        }
    }
}

// ---------------- small fallback GEMM (guarded, for N=84 / N=21 heads) -------
#define BM 64
#define BN 64
#define BK 16
#define SPAD 68
__global__ void __launch_bounds__(256) gemm_small_kernel(
    const float* __restrict__ A, const float* __restrict__ B, float* __restrict__ C,
    int M, int N, int K, int lda, int ldb, int ldc,
    const float* __restrict__ bias)
{
    __shared__ __align__(16) float As[BK][SPAD];
    __shared__ __align__(16) float Bs[BK][SPAD];
    int m0 = blockIdx.y * BM;
    int n0 = blockIdx.x * BN;
    int tid = threadIdx.x;
    int tx = tid & 15, ty = tid >> 4;
    float acc[4][4] = {};
    for (int kt = 0; kt < K; kt += BK) {
        {
            int kk = tid & 15, mm = tid >> 4;
#pragma unroll
            for (int p = 0; p < 4; p++) {
                int m = mm + p * 16;
                As[kk][m] = A[(size_t)(m0 + m) * lda + (kt + kk)];
            }
        }
        {
            int nn = tid & 63, kk = tid >> 6;
#pragma unroll
            for (int p = 0; p < 4; p++) {
                int k = kk + p * 4;
                int gn = n0 + nn;
                Bs[k][nn] = (gn < N) ? B[(size_t)(kt + k) * ldb + gn] : 0.f;
            }
        }
        __syncthreads();
#pragma unroll
        for (int kk = 0; kk < BK; kk++) {
            float4 a4 = *reinterpret_cast<const float4*>(&As[kk][ty * 4]);
            float4 b4 = *reinterpret_cast<const float4*>(&Bs[kk][tx * 4]);
            float a[4] = {a4.x, a4.y, a4.z, a4.w};
            float b[4] = {b4.x, b4.y, b4.z, b4.w};
#pragma unroll
            for (int i = 0; i < 4; i++)
#pragma unroll
                for (int j = 0; j < 4; j++)
                    acc[i][j] = fmaf(a[i], b[j], acc[i][j]);
        }
        __syncthreads();
    }
#pragma unroll
    for (int i = 0; i < 4; i++) {
        int gm = m0 + ty * 4 + i;
#pragma unroll
        for (int j = 0; j < 4; j++) {
            int gn = n0 + tx * 4 + j;
            if (gn < N) C[(size_t)gm * ldc + gn] = acc[i][j] + bias[gn];
        }
    }
}

__global__ void reduceK_kernel(const float* __restrict__ part, float* __restrict__ outb,
                               int total, int parts) {
    int i = blockIdx.x * blockDim.x + threadIdx.x;
    if (i >= total) return;
    float s = 0.f;
    for (int p = 0; p < parts; p++) s += part[(size_t)p * total + i];
    outb[i] = s;
}

// ---------------- softmax over 21 classes, one warp per row ------------------
__global__ void softmax_kernel(float* __restrict__ out) {
    int row = blockIdx.x * 8 + (threadIdx.x >> 5);
    int lane = threadIdx.x & 31;
    if (row >= NROI) return;
    float v = (lane < NCLS) ? g_logits[row * NCLS + lane] : -INFINITY;
    float m = v;
#pragma unroll
    for (int o = 16; o; o >>= 1) m = fmaxf(m, __shfl_xor_sync(0xffffffffu, m, o));
    float e = (lane < NCLS) ? expf(v - m) : 0.f;
    float s = e;
#pragma unroll
    for (int o = 16; o; o >>= 1) s += __shfl_xor_sync(0xffffffffu, s, o);
    if (lane < NCLS) out[NROI + row * NCLS + lane] = e / s;
}

// -----------------------------------------------------------------------------
extern "C" void kernel_launch(void* const* d_in, const int* in_sizes, int n_in,
                              void* d_out, int out_size) {
    const float* rois   = (const float*)d_in[0];
    const float* pf     = (const float*)d_in[1];
    const float* Wg1    = (const float*)d_in[2];
    const float* bg1    = (const float*)d_in[3];
    const float* Wg2    = (const float*)d_in[4];
    const float* bg2    = (const float*)d_in[5];
    const float* W_bbox = (const float*)d_in[6];
    const float* b_bbox = (const float*)d_in[7];
    const float* W_cls  = (const float*)d_in[8];
    const float* b_cls  = (const float*)d_in[9];
    float* out = (float*)d_out;

    float *xn, *dv, *t1, *u1, *u2, *upart, *h1, *t2, *h2, *logits;
    cudaGetSymbolAddress((void**)&xn,     g_xn);
    cudaGetSymbolAddress((void**)&dv,     g_d);
    cudaGetSymbolAddress((void**)&t1,     g_t1);
    cudaGetSymbolAddress((void**)&u1,     g_u1);
    cudaGetSymbolAddress((void**)&u2,     g_u2);
    cudaGetSymbolAddress((void**)&upart,  g_upart);
    cudaGetSymbolAddress((void**)&h1,     g_h1);
    cudaGetSymbolAddress((void**)&t2,     g_t2);
    cudaGetSymbolAddress((void**)&h2,     g_h2);
    cudaGetSymbolAddress((void**)&logits, g_logits);

    const int utotal = DIM * HID;

    // Launch order: ncu (-s 5 -c 1) profiles launch #6 = h1 GEMM.
    normalize_kernel<<<NROI, 256>>>(pf);                               // 1
    adj_kernel<<<NROI / 16, 256>>>(rois);                              // 2

    // t1 = pooled @ Wg1     [4096,512] K=1024
    gemm2_kernel<false, 0><<<dim3(HID / GBN, NROI / GBM, 1), 256>>>(   // 3
        pf, Wg1, t1, NROI, HID, DIM, DIM, HID, HID, DIM, nullptr, nullptr, nullptr);

    // u1 = xn^T @ t1        [1024,512] K=4096, split-K
    gemm2_kernel<true, 0><<<dim3(HID / GBN, DIM / GBM, KSPLIT), 256>>>( // 4
        xn, t1, upart, DIM, HID, NROI, DIM, HID, HID, NROI / KSPLIT,
        nullptr, nullptr, nullptr);
    reduceK_kernel<<<(utotal + 255) / 256, 256>>>(upart, u1, utotal, KSPLIT); // 5

    // h1 = relu(xn @ u1 - d*t1 + bg1)
    gemm2_kernel<false, 1><<<dim3(HID / GBN, NROI / GBM, 1), 256>>>(   // 6 <- profiled
        xn, u1, h1, NROI, HID, DIM, DIM, HID, HID, DIM, bg1, dv, t1);

    // t2 = h1 @ Wg2         [4096,512] K=512
    gemm2_kernel<false, 0><<<dim3(HID / GBN, NROI / GBM, 1), 256>>>(
        h1, Wg2, t2, NROI, HID, HID, HID, HID, HID, HID, nullptr, nullptr, nullptr);

    // u2 = xn^T @ t2
    gemm2_kernel<true, 0><<<dim3(HID / GBN, DIM / GBM, KSPLIT), 256>>>(
        xn, t2, upart, DIM, HID, NROI, DIM, HID, HID, NROI / KSPLIT,
        nullptr, nullptr, nullptr);
    reduceK_kernel<<<(utotal + 255) / 256, 256>>>(upart, u2, utotal, KSPLIT);

    // h2 = relu(xn @ u2 - d*t2 + bg2)
    gemm2_kernel<false, 1><<<dim3(HID / GBN, NROI / GBM, 1), 256>>>(
        xn, u2, h2, NROI, HID, DIM, DIM, HID, HID, DIM, bg2, dv, t2);

    // bbox_pred = h2 @ W_bbox + b_bbox
    gemm_small_kernel<<<dim3((NBBX + BN - 1) / BN, NROI / BM, 1), 256>>>(
        h2, W_bbox, out + NROI + (size_t)NROI * NCLS,
        NROI, NBBX, HID, HID, NBBX, NBBX, b_bbox);

    // cls logits + softmax
    gemm_small_kernel<<<dim3(1, NROI / BM, 1), 256>>>(
        h2, W_cls, logits, NROI, NCLS, HID, HID, NCLS, NCLS, b_cls);
    softmax_kernel<<<NROI / 8, 256>>>(out);

    // ---- connected components (32 fused prop iterations, early exit) ----
    init_labels_kernel<<<17, 256>>>();
    for (int it = 0; it < 32; it++)
        prop_kernel<<<NROI / 32, 256>>>(it, it & 1);
    labels_out_kernel<<<16, 256>>>(out);
}